// round 10
// baseline (speedup 1.0000x reference)
#include <cuda_runtime.h>
#include <math.h>
#include <stdint.h>

#define NROWS 65536
#define DIMV  512
#define CD    10
#define NQ    8
#define OUT_ELEMS   (NROWS * DIMV)
#define IDX_ELEMS   (NROWS * NQ)
#define LOSS_OFFSET (OUT_ELEMS + IDX_ELEMS)

__device__ __align__(16) float g_ptab[(size_t)NQ * NROWS * CD];  // [q][row][d]
__device__ __align__(16) float g_h[(size_t)NROWS * CD];          // [row][d]
__device__ __align__(16) float g_qo[(size_t)NROWS * CD];         // [row][d]
__device__ __align__(16) float g_codesum[NQ * 1024];
__device__ float g_psent[NQ];
__device__ float g_commit[NQ];

// packed f32x2 FMA (sm_100a)
__device__ __forceinline__ void fma2(unsigned long long& acc,
                                     unsigned long long a,
                                     unsigned long long b) {
    asm("fma.rn.f32x2 %0, %1, %2, %0;" : "+l"(acc) : "l"(a), "l"(b));
}
__device__ __forceinline__ unsigned long long dup2(float v) {
    unsigned long long r;
    asm("mov.b64 %0, {%1, %1};" : "=l"(r) : "f"(v));
    return r;
}

// ---------------------------------------------------------------------------
__global__ void k_zero() {
    int t = blockIdx.x * blockDim.x + threadIdx.x;
    if (t < NQ * 1024) g_codesum[t] = 0.f;
    if (t < NQ) { g_psent[t] = 0.f; g_commit[t] = 0.f; }
}

__global__ void k_pad() {}   // keeps kA in ncu's profiled slot (slot 4)

// ---------------------------------------------------------------------------
// kA v4: h = x @ w_in + b_in. Warp = 2 consecutive rows (register-safe: ~70).
// Lane owns cols {k*128 + lane*4}; same per-lane serial-16 + butterfly order
// as R8 -> h bit-identical to the passing kernel.
__global__ void __launch_bounds__(256, 3) kA(
    const float* __restrict__ x,
    const float* __restrict__ w_in,
    const float* __restrict__ b_in)
{
    __shared__ __align__(16) float ws_t[CD * DIMV];   // transposed w_in [d][col]
    __shared__ float bis[16];

    const int tid = threadIdx.x;
    for (int i = tid; i < DIMV; i += 256) {
        #pragma unroll
        for (int d = 0; d < CD; d++) ws_t[d * DIMV + i] = w_in[i * CD + d];
    }
    if (tid < CD) bis[tid] = b_in[tid];
    __syncthreads();

    const int lane = tid & 31;
    const unsigned FULL = 0xffffffffu;
    const int gwarp = blockIdx.x * 8 + (tid >> 5);    // 16384 warps, 2 pairs each

    for (int pair = gwarp; pair < NROWS / 2; pair += 16384) {
        const int row0 = pair * 2;
        const float* xr = x + (size_t)row0 * DIMV;

        // 8 independent, fully-coalesced 512B loads (2 rows x 4 chunks)
        float4 xv[2][4];
        #pragma unroll
        for (int m = 0; m < 2; m++)
            #pragma unroll
            for (int k = 0; k < 4; k++)
                xv[m][k] = *(const float4*)(xr + (size_t)m * DIMV + k * 128 + lane * 4);

        float h[2][CD];
        #pragma unroll
        for (int m = 0; m < 2; m++)
            #pragma unroll
            for (int d = 0; d < CD; d++) h[m][d] = 0.f;

        #pragma unroll
        for (int k = 0; k < 4; k++) {
            #pragma unroll
            for (int d = 0; d < CD; d++) {
                float4 w = *(const float4*)(ws_t + d * DIMV + k * 128 + lane * 4);
                #pragma unroll
                for (int m = 0; m < 2; m++) {
                    h[m][d] = fmaf(xv[m][k].x, w.x, h[m][d]);
                    h[m][d] = fmaf(xv[m][k].y, w.y, h[m][d]);
                    h[m][d] = fmaf(xv[m][k].z, w.z, h[m][d]);
                    h[m][d] = fmaf(xv[m][k].w, w.w, h[m][d]);
                }
            }
        }

        // 5-stage butterfly over 20 sums (100 SHFL)
        #pragma unroll
        for (int m = 0; m < 2; m++)
            #pragma unroll
            for (int d = 0; d < CD; d++)
                #pragma unroll
                for (int off = 16; off > 0; off >>= 1)
                    h[m][d] += __shfl_xor_sync(FULL, h[m][d], off);

        // lanes 0..19 store: m = lane/10, d = lane%10 (20 contiguous floats)
        if (lane < 20) {
            int m = lane / 10;
            int d = lane - m * 10;
            float v = 0.f;
            #pragma unroll
            for (int mm = 0; mm < 2; mm++)
                #pragma unroll
                for (int dd = 0; dd < CD; dd++)
                    if (lane == mm * 10 + dd) v = h[mm][dd];
            g_h[(size_t)(row0 + m) * CD + d] = v + bis[d];
        }
    }
}

// ---------------------------------------------------------------------------
// kB: 8x LFQ on h. One quad per warp. (R8 verbatim — known correct.)
__global__ void __launch_bounds__(256, 4) kB(float* __restrict__ out_idx)
{
    __shared__ float red_ps[8][NQ];
    __shared__ float red_cm[8][NQ];

    const int tid = threadIdx.x;
    const int lane = tid & 31;
    const int wid  = tid >> 5;
    const int half = lane >> 4;
    const int hl   = lane & 15;
    const unsigned FULL = 0xffffffffu;

    const int quad = blockIdx.x * 8 + wid;
    const int row0 = quad * 4;
    const int row_a = row0 + 2 * half;

    float ra = 0.f, rb = 0.f;
    if (hl < CD) {
        ra = g_h[(size_t)row_a * CD + hl];
        rb = g_h[(size_t)(row_a + 1) * CD + hl];
    }

    float psent[NQ], commit[NQ];
    #pragma unroll
    for (int q = 0; q < NQ; q++) { psent[q] = 0.f; commit[q] = 0.f; }

    float qo_a = 0.f, qo_b = 0.f, iv_a = 0.f, iv_b = 0.f;

    #pragma unroll
    for (int q = 0; q < NQ; q++) {
        const float scale = 1.0f / (float)(1 << q);

        #define QSTEP(R, QO, IV, ROW)                                           \
        {                                                                       \
            bool pos = (R) > 0.f;                                               \
            unsigned bl = __ballot_sync(FULL, pos);                             \
            int idx = (int)(__brev((bl >> (half * 16)) & 0x3FFu) >> 22);        \
            if (hl == q) (IV) = (float)idx;                                     \
            float qv = pos ? scale : -scale;                                    \
            float dlt = (R) - qv;                                               \
            if (hl < CD) {                                                      \
                float a = 400.f * scale * (R);                                  \
                float t = fabsf(a);                                             \
                float e = __expf(-t);                                           \
                float inv = __fdividef(1.f, 1.f + e);                           \
                float p = (a > 0.f) ? inv : e * inv;                            \
                commit[q] += dlt * dlt;                                         \
                psent[q] += __logf(1.f + e) + t * e * inv;                      \
                g_ptab[((size_t)q * NROWS + (ROW)) * CD + hl] = p;              \
            }                                                                   \
            (R) = dlt;                                                          \
            (QO) += qv;                                                         \
        }

        QSTEP(ra, qo_a, iv_a, row_a)
        QSTEP(rb, qo_b, iv_b, row_a + 1)
        #undef QSTEP
    }

    if (hl < NQ) {
        out_idx[(size_t)row_a * NQ + hl]       = iv_a;
        out_idx[(size_t)(row_a + 1) * NQ + hl] = iv_b;
    }
    if (hl < CD) {
        g_qo[(size_t)row_a * CD + hl]       = qo_a;
        g_qo[(size_t)(row_a + 1) * CD + hl] = qo_b;
    }

    #pragma unroll
    for (int q = 0; q < NQ; q++) {
        float v = psent[q], c = commit[q];
        #pragma unroll
        for (int off = 16; off > 0; off >>= 1) {
            v += __shfl_xor_sync(FULL, v, off);
            c += __shfl_xor_sync(FULL, c, off);
        }
        if (lane == 0) { red_ps[wid][q] = v; red_cm[wid][q] = c; }
    }
    __syncthreads();
    if (tid < NQ * 2) {
        int q = tid & 7;
        bool isC = tid >= NQ;
        float s = 0.f;
        #pragma unroll
        for (int w = 0; w < 8; w++) s += isC ? red_cm[w][q] : red_ps[w][q];
        atomicAdd(isC ? &g_commit[q] : &g_psent[q], s);
    }
}

// ---------------------------------------------------------------------------
// k2c: fused. Blocks [0,512): out-GEMM (BW-bound).
//             Blocks [512,1536): codesum (issue-bound, f32x2).
__global__ void __launch_bounds__(256, 3) k2c(
    const float* __restrict__ w_out,
    const float* __restrict__ b_out,
    float* __restrict__ out)
{
    const int t = threadIdx.x;

    if (blockIdx.x < 512) {
        __shared__ __align__(16) float qo_s[128 * CD];
        const int j4 = t & 127;
        const int halfr = t >> 7;
        const int rows0 = blockIdx.x * 128;

        float4 w[CD];
        #pragma unroll
        for (int d = 0; d < CD; d++) w[d] = ((const float4*)w_out)[d * 128 + j4];
        float4 b4 = ((const float4*)b_out)[j4];

        const float4* src = (const float4*)(g_qo + (size_t)rows0 * CD);
        for (int i = t; i < 320; i += 256) ((float4*)qo_s)[i] = src[i];
        __syncthreads();

        float4* outv = (float4*)out;
        #pragma unroll 4
        for (int i = 0; i < 64; i += 2) {
            int r0 = 2 * i + halfr;
            int r1 = r0 + 2;
            float4 a0 = b4, a1 = b4;
            #pragma unroll
            for (int d = 0; d < CD; d++) {
                float q0 = qo_s[r0 * CD + d];
                float q1 = qo_s[r1 * CD + d];
                a0.x = fmaf(q0, w[d].x, a0.x);
                a0.y = fmaf(q0, w[d].y, a0.y);
                a0.z = fmaf(q0, w[d].z, a0.z);
                a0.w = fmaf(q0, w[d].w, a0.w);
                a1.x = fmaf(q1, w[d].x, a1.x);
                a1.y = fmaf(q1, w[d].y, a1.y);
                a1.z = fmaf(q1, w[d].z, a1.z);
                a1.w = fmaf(q1, w[d].w, a1.w);
            }
            outv[(size_t)(rows0 + r0) * 128 + j4] = a0;
            outv[(size_t)(rows0 + r1) * 128 + j4] = a1;
        }
    } else {
        const int b = blockIdx.x - 512;
        const int q = b >> 7;
        const int chunk = b & 127;
        const int row0 = chunk * 512;

        __shared__ float ps_s[32 * CD];
        __shared__ __align__(16) float hlb[32][64];
        __shared__ float codebuf[1024];

        for (int i = t; i < 1024; i += 256) codebuf[i] = 0.f;

        const int cls = t & 31;
        const int wid = t >> 5;
        const int hi4 = (cls >> 2) * 4;
        const int lo8 = (cls & 3) * 8;

        unsigned long long acc2[4][4];
        #pragma unroll
        for (int i = 0; i < 4; i++)
            #pragma unroll
            for (int j = 0; j < 4; j++) acc2[i][j] = 0ULL;

        const float* pt = g_ptab + (size_t)q * NROWS * CD + (size_t)row0 * CD;

        float nxt0 = pt[t];
        float nxt1 = (t < 64) ? pt[256 + t] : 0.f;

        for (int tile = 0; tile < 16; tile++) {
            ps_s[t] = nxt0;
            if (t < 64) ps_s[256 + t] = nxt1;
            __syncthreads();

            if (tile < 15) {
                const float* nb = pt + (tile + 1) * 320;
                nxt0 = nb[t];
                if (t < 64) nxt1 = nb[256 + t];
            }

            #pragma unroll
            for (int task = t; task < 512; task += 256) {
                int rl = task >> 4;
                int v0 = (task & 15) * 4;
                bool isHi = (v0 < 32);
                int dbase = isHi ? 0 : 5;
                int vb = isHi ? v0 : (v0 - 32);
                const float* pr = ps_s + rl * CD + dbase;
                float p0 = pr[0], p1 = pr[1], p2 = pr[2], p3 = pr[3], p4 = pr[4];
                float n0 = 1.f - p0, n1 = 1.f - p1, n2 = 1.f - p2, n3 = 1.f - p3, n4 = 1.f - p4;
                float4 res;
                float* rp = &res.x;
                #pragma unroll
                for (int j = 0; j < 4; j++) {
                    int v = vb + j;
                    float val = ((v & 16) ? p0 : n0);
                    val *= ((v & 8) ? p1 : n1);
                    val *= ((v & 4) ? p2 : n2);
                    val *= ((v & 2) ? p3 : n3);
                    val *= ((v & 1) ? p4 : n4);
                    rp[j] = val;
                }
                *(float4*)&hlb[rl][v0] = res;
            }
            __syncthreads();

            #pragma unroll
            for (int rr = 0; rr < 4; rr++) {
                int rl = wid * 4 + rr;
                float4 hv = *(const float4*)&hlb[rl][hi4];
                ulonglong2 la = *(const ulonglong2*)&hlb[rl][32 + lo8];
                ulonglong2 lb = *(const ulonglong2*)&hlb[rl][32 + lo8 + 4];

                unsigned long long d0 = dup2(hv.x);
                unsigned long long d1 = dup2(hv.y);
                unsigned long long d2 = dup2(hv.z);
                unsigned long long d3 = dup2(hv.w);

                fma2(acc2[0][0], d0, la.x); fma2(acc2[0][1], d0, la.y);
                fma2(acc2[0][2], d0, lb.x); fma2(acc2[0][3], d0, lb.y);
                fma2(acc2[1][0], d1, la.x); fma2(acc2[1][1], d1, la.y);
                fma2(acc2[1][2], d1, lb.x); fma2(acc2[1][3], d1, lb.y);
                fma2(acc2[2][0], d2, la.x); fma2(acc2[2][1], d2, la.y);
                fma2(acc2[2][2], d2, lb.x); fma2(acc2[2][3], d2, lb.y);
                fma2(acc2[3][0], d3, la.x); fma2(acc2[3][1], d3, la.y);
                fma2(acc2[3][2], d3, lb.x); fma2(acc2[3][3], d3, lb.y);
            }
            __syncthreads();
        }

        #pragma unroll
        for (int i = 0; i < 4; i++) {
            #pragma unroll
            for (int j = 0; j < 4; j++) {
                float vlo = __uint_as_float((unsigned)(acc2[i][j] & 0xffffffffu));
                float vhi = __uint_as_float((unsigned)(acc2[i][j] >> 32));
                int code = (hi4 + i) * 32 + lo8 + 2 * j;
                atomicAdd(&codebuf[code], vlo);
                atomicAdd(&codebuf[code + 1], vhi);
            }
        }
        __syncthreads();
        for (int i = t; i < 1024; i += 256)
            atomicAdd(&g_codesum[q * 1024 + i], codebuf[i]);
    }
}

// ---------------------------------------------------------------------------
__global__ void k_fin(float* __restrict__ loss_out) {
    __shared__ float red[256];
    const int q = blockIdx.x;
    const int t = threadIdx.x;
    float e = 0.f;
    #pragma unroll
    for (int k = 0; k < 4; k++) {
        int c = k * 256 + t;
        float avg = g_codesum[q * 1024 + c] * (1.0f / (float)NROWS);
        e -= avg * __logf(fmaxf(avg, 1e-20f));
    }
    red[t] = e;
    __syncthreads();
    for (int s = 128; s > 0; s >>= 1) {
        if (t < s) red[t] += red[t + s];
        __syncthreads();
    }
    if (t == 0) {
        float per_sample = g_psent[q] * (1.0f / (float)NROWS);
        float ent_aux = per_sample - red[0];
        float commit = g_commit[q] * (1.0f / (float)(NROWS * CD));
        loss_out[q] = ent_aux * 0.1f + commit * 0.25f;
    }
}

// ---------------------------------------------------------------------------
extern "C" void kernel_launch(void* const* d_in, const int* in_sizes, int n_in,
                              void* d_out, int out_size) {
    const float* x     = (const float*)d_in[0];
    const float* w_in  = (const float*)d_in[1];
    const float* b_in  = (const float*)d_in[2];
    const float* w_out = (const float*)d_in[3];
    const float* b_out = (const float*)d_in[4];

    float* out  = (float*)d_out;
    float* idx  = out + OUT_ELEMS;
    float* loss = out + LOSS_OFFSET;

    k_zero<<<32, 256>>>();                        // 1
    k_pad<<<1, 32>>>();                           // 2
    k_pad<<<1, 32>>>();                           // 3
    kA<<<2048, 256>>>(x, w_in, b_in);             // 4  <- ncu slot
    kB<<<2048, 256>>>(idx);                       // 5
    k2c<<<1536, 256>>>(w_out, b_out, out);        // 6
    k_fin<<<8, 256>>>(loss);                      // 7
}

// round 11
// speedup vs baseline: 1.3742x; 1.3742x over previous
#include <cuda_runtime.h>
#include <math.h>
#include <stdint.h>

#define NROWS 65536
#define DIMV  512
#define CD    10
#define NQ    8
#define OUT_ELEMS   (NROWS * DIMV)
#define IDX_ELEMS   (NROWS * NQ)
#define LOSS_OFFSET (OUT_ELEMS + IDX_ELEMS)

__device__ __align__(16) float g_ptab[(size_t)NQ * NROWS * CD];  // [q][row][d]
__device__ __align__(16) float g_h[(size_t)NROWS * CD];          // [row][d]
__device__ __align__(16) float g_qo[(size_t)NROWS * CD];         // [row][d]
__device__ __align__(16) float g_codesum[NQ * 1024];
__device__ float g_psent[NQ];
__device__ float g_commit[NQ];

// packed f32x2 FMA (sm_100a)
__device__ __forceinline__ void fma2(unsigned long long& acc,
                                     unsigned long long a,
                                     unsigned long long b) {
    asm("fma.rn.f32x2 %0, %1, %2, %0;" : "+l"(acc) : "l"(a), "l"(b));
}
__device__ __forceinline__ unsigned long long dup2(float v) {
    unsigned long long r;
    asm("mov.b64 %0, {%1, %1};" : "=l"(r) : "f"(v));
    return r;
}

// ---------------------------------------------------------------------------
__global__ void k_zero() {
    int t = blockIdx.x * blockDim.x + threadIdx.x;
    if (t < NQ * 1024) g_codesum[t] = 0.f;
    if (t < NQ) { g_psent[t] = 0.f; g_commit[t] = 0.f; }
}

__global__ void k_pad() {}   // keeps kA in ncu's profiled slot (slot 4)

// ---------------------------------------------------------------------------
// kA v5: h = x @ w_in + b_in. Warp = 2 rows. Software-pipelined: next pair's
// 8 LDGs issue before current pair's compute -> DRAM latency overlaps
// FMA + LDS + butterfly. Math order identical to R10 (bit-exact h).
#define NPAIR_PER_WARP 4
#define WARPS_TOTAL    8192
__global__ void __launch_bounds__(256, 2) kA(
    const float* __restrict__ x,
    const float* __restrict__ w_in,
    const float* __restrict__ b_in)
{
    __shared__ __align__(16) float ws_t[CD * DIMV];   // transposed w_in [d][col]
    __shared__ float bis[16];

    const int tid = threadIdx.x;
    for (int i = tid; i < DIMV; i += 256) {
        #pragma unroll
        for (int d = 0; d < CD; d++) ws_t[d * DIMV + i] = w_in[i * CD + d];
    }
    if (tid < CD) bis[tid] = b_in[tid];
    __syncthreads();

    const int lane = tid & 31;
    const unsigned FULL = 0xffffffffu;
    const int gwarp = blockIdx.x * 8 + (tid >> 5);    // 8192 warps

    // prefetch pair 0
    float4 xc[2][4];
    {
        const float* xr = x + (size_t)(gwarp * 2) * DIMV;
        #pragma unroll
        for (int m = 0; m < 2; m++)
            #pragma unroll
            for (int k = 0; k < 4; k++)
                xc[m][k] = *(const float4*)(xr + (size_t)m * DIMV + k * 128 + lane * 4);
    }

    #pragma unroll
    for (int it = 0; it < NPAIR_PER_WARP; it++) {
        const int pair = gwarp + it * WARPS_TOTAL;
        const int row0 = pair * 2;

        // issue next pair's loads BEFORE consuming current registers
        float4 xn[2][4];
        if (it < NPAIR_PER_WARP - 1) {
            const float* xr2 = x + (size_t)(row0 + 2 * WARPS_TOTAL) * DIMV;
            #pragma unroll
            for (int m = 0; m < 2; m++)
                #pragma unroll
                for (int k = 0; k < 4; k++)
                    xn[m][k] = *(const float4*)(xr2 + (size_t)m * DIMV + k * 128 + lane * 4);
        }

        // ---- compute current pair (identical order to R10) ----
        float h[2][CD];
        #pragma unroll
        for (int m = 0; m < 2; m++)
            #pragma unroll
            for (int d = 0; d < CD; d++) h[m][d] = 0.f;

        #pragma unroll
        for (int k = 0; k < 4; k++) {
            #pragma unroll
            for (int d = 0; d < CD; d++) {
                float4 w = *(const float4*)(ws_t + d * DIMV + k * 128 + lane * 4);
                #pragma unroll
                for (int m = 0; m < 2; m++) {
                    h[m][d] = fmaf(xc[m][k].x, w.x, h[m][d]);
                    h[m][d] = fmaf(xc[m][k].y, w.y, h[m][d]);
                    h[m][d] = fmaf(xc[m][k].z, w.z, h[m][d]);
                    h[m][d] = fmaf(xc[m][k].w, w.w, h[m][d]);
                }
            }
        }

        // 5-stage butterfly over 20 sums
        #pragma unroll
        for (int m = 0; m < 2; m++)
            #pragma unroll
            for (int d = 0; d < CD; d++)
                #pragma unroll
                for (int off = 16; off > 0; off >>= 1)
                    h[m][d] += __shfl_xor_sync(FULL, h[m][d], off);

        // lanes 0..19 store: m = lane/10, d = lane%10
        if (lane < 20) {
            int m = lane / 10;
            int d = lane - m * 10;
            float v = 0.f;
            #pragma unroll
            for (int mm = 0; mm < 2; mm++)
                #pragma unroll
                for (int dd = 0; dd < CD; dd++)
                    if (lane == mm * 10 + dd) v = h[mm][dd];
            g_h[(size_t)(row0 + m) * CD + d] = v + bis[d];
        }

        // rotate buffers (renamed away by full unroll)
        if (it < NPAIR_PER_WARP - 1) {
            #pragma unroll
            for (int m = 0; m < 2; m++)
                #pragma unroll
                for (int k = 0; k < 4; k++)
                    xc[m][k] = xn[m][k];
        }
    }
}

// ---------------------------------------------------------------------------
// kB: 8x LFQ on h. One quad per warp. (unchanged — known correct)
__global__ void __launch_bounds__(256, 4) kB(float* __restrict__ out_idx)
{
    __shared__ float red_ps[8][NQ];
    __shared__ float red_cm[8][NQ];

    const int tid = threadIdx.x;
    const int lane = tid & 31;
    const int wid  = tid >> 5;
    const int half = lane >> 4;
    const int hl   = lane & 15;
    const unsigned FULL = 0xffffffffu;

    const int quad = blockIdx.x * 8 + wid;
    const int row0 = quad * 4;
    const int row_a = row0 + 2 * half;

    float ra = 0.f, rb = 0.f;
    if (hl < CD) {
        ra = g_h[(size_t)row_a * CD + hl];
        rb = g_h[(size_t)(row_a + 1) * CD + hl];
    }

    float psent[NQ], commit[NQ];
    #pragma unroll
    for (int q = 0; q < NQ; q++) { psent[q] = 0.f; commit[q] = 0.f; }

    float qo_a = 0.f, qo_b = 0.f, iv_a = 0.f, iv_b = 0.f;

    #pragma unroll
    for (int q = 0; q < NQ; q++) {
        const float scale = 1.0f / (float)(1 << q);

        #define QSTEP(R, QO, IV, ROW)                                           \
        {                                                                       \
            bool pos = (R) > 0.f;                                               \
            unsigned bl = __ballot_sync(FULL, pos);                             \
            int idx = (int)(__brev((bl >> (half * 16)) & 0x3FFu) >> 22);        \
            if (hl == q) (IV) = (float)idx;                                     \
            float qv = pos ? scale : -scale;                                    \
            float dlt = (R) - qv;                                               \
            if (hl < CD) {                                                      \
                float a = 400.f * scale * (R);                                  \
                float t = fabsf(a);                                             \
                float e = __expf(-t);                                           \
                float inv = __fdividef(1.f, 1.f + e);                           \
                float p = (a > 0.f) ? inv : e * inv;                            \
                commit[q] += dlt * dlt;                                         \
                psent[q] += __logf(1.f + e) + t * e * inv;                      \
                g_ptab[((size_t)q * NROWS + (ROW)) * CD + hl] = p;              \
            }                                                                   \
            (R) = dlt;                                                          \
            (QO) += qv;                                                         \
        }

        QSTEP(ra, qo_a, iv_a, row_a)
        QSTEP(rb, qo_b, iv_b, row_a + 1)
        #undef QSTEP
    }

    if (hl < NQ) {
        out_idx[(size_t)row_a * NQ + hl]       = iv_a;
        out_idx[(size_t)(row_a + 1) * NQ + hl] = iv_b;
    }
    if (hl < CD) {
        g_qo[(size_t)row_a * CD + hl]       = qo_a;
        g_qo[(size_t)(row_a + 1) * CD + hl] = qo_b;
    }

    #pragma unroll
    for (int q = 0; q < NQ; q++) {
        float v = psent[q], c = commit[q];
        #pragma unroll
        for (int off = 16; off > 0; off >>= 1) {
            v += __shfl_xor_sync(FULL, v, off);
            c += __shfl_xor_sync(FULL, c, off);
        }
        if (lane == 0) { red_ps[wid][q] = v; red_cm[wid][q] = c; }
    }
    __syncthreads();
    if (tid < NQ * 2) {
        int q = tid & 7;
        bool isC = tid >= NQ;
        float s = 0.f;
        #pragma unroll
        for (int w = 0; w < 8; w++) s += isC ? red_cm[w][q] : red_ps[w][q];
        atomicAdd(isC ? &g_commit[q] : &g_psent[q], s);
    }
}

// ---------------------------------------------------------------------------
// k2c: fused. Blocks [0,512): out-GEMM. Blocks [512,1536): codesum. (unchanged)
__global__ void __launch_bounds__(256, 3) k2c(
    const float* __restrict__ w_out,
    const float* __restrict__ b_out,
    float* __restrict__ out)
{
    const int t = threadIdx.x;

    if (blockIdx.x < 512) {
        __shared__ __align__(16) float qo_s[128 * CD];
        const int j4 = t & 127;
        const int halfr = t >> 7;
        const int rows0 = blockIdx.x * 128;

        float4 w[CD];
        #pragma unroll
        for (int d = 0; d < CD; d++) w[d] = ((const float4*)w_out)[d * 128 + j4];
        float4 b4 = ((const float4*)b_out)[j4];

        const float4* src = (const float4*)(g_qo + (size_t)rows0 * CD);
        for (int i = t; i < 320; i += 256) ((float4*)qo_s)[i] = src[i];
        __syncthreads();

        float4* outv = (float4*)out;
        #pragma unroll 4
        for (int i = 0; i < 64; i += 2) {
            int r0 = 2 * i + halfr;
            int r1 = r0 + 2;
            float4 a0 = b4, a1 = b4;
            #pragma unroll
            for (int d = 0; d < CD; d++) {
                float q0 = qo_s[r0 * CD + d];
                float q1 = qo_s[r1 * CD + d];
                a0.x = fmaf(q0, w[d].x, a0.x);
                a0.y = fmaf(q0, w[d].y, a0.y);
                a0.z = fmaf(q0, w[d].z, a0.z);
                a0.w = fmaf(q0, w[d].w, a0.w);
                a1.x = fmaf(q1, w[d].x, a1.x);
                a1.y = fmaf(q1, w[d].y, a1.y);
                a1.z = fmaf(q1, w[d].z, a1.z);
                a1.w = fmaf(q1, w[d].w, a1.w);
            }
            outv[(size_t)(rows0 + r0) * 128 + j4] = a0;
            outv[(size_t)(rows0 + r1) * 128 + j4] = a1;
        }
    } else {
        const int b = blockIdx.x - 512;
        const int q = b >> 7;
        const int chunk = b & 127;
        const int row0 = chunk * 512;

        __shared__ float ps_s[32 * CD];
        __shared__ __align__(16) float hlb[32][64];
        __shared__ float codebuf[1024];

        for (int i = t; i < 1024; i += 256) codebuf[i] = 0.f;

        const int cls = t & 31;
        const int wid = t >> 5;
        const int hi4 = (cls >> 2) * 4;
        const int lo8 = (cls & 3) * 8;

        unsigned long long acc2[4][4];
        #pragma unroll
        for (int i = 0; i < 4; i++)
            #pragma unroll
            for (int j = 0; j < 4; j++) acc2[i][j] = 0ULL;

        const float* pt = g_ptab + (size_t)q * NROWS * CD + (size_t)row0 * CD;

        float nxt0 = pt[t];
        float nxt1 = (t < 64) ? pt[256 + t] : 0.f;

        for (int tile = 0; tile < 16; tile++) {
            ps_s[t] = nxt0;
            if (t < 64) ps_s[256 + t] = nxt1;
            __syncthreads();

            if (tile < 15) {
                const float* nb = pt + (tile + 1) * 320;
                nxt0 = nb[t];
                if (t < 64) nxt1 = nb[256 + t];
            }

            #pragma unroll
            for (int task = t; task < 512; task += 256) {
                int rl = task >> 4;
                int v0 = (task & 15) * 4;
                bool isHi = (v0 < 32);
                int dbase = isHi ? 0 : 5;
                int vb = isHi ? v0 : (v0 - 32);
                const float* pr = ps_s + rl * CD + dbase;
                float p0 = pr[0], p1 = pr[1], p2 = pr[2], p3 = pr[3], p4 = pr[4];
                float n0 = 1.f - p0, n1 = 1.f - p1, n2 = 1.f - p2, n3 = 1.f - p3, n4 = 1.f - p4;
                float4 res;
                float* rp = &res.x;
                #pragma unroll
                for (int j = 0; j < 4; j++) {
                    int v = vb + j;
                    float val = ((v & 16) ? p0 : n0);
                    val *= ((v & 8) ? p1 : n1);
                    val *= ((v & 4) ? p2 : n2);
                    val *= ((v & 2) ? p3 : n3);
                    val *= ((v & 1) ? p4 : n4);
                    rp[j] = val;
                }
                *(float4*)&hlb[rl][v0] = res;
            }
            __syncthreads();

            #pragma unroll
            for (int rr = 0; rr < 4; rr++) {
                int rl = wid * 4 + rr;
                float4 hv = *(const float4*)&hlb[rl][hi4];
                ulonglong2 la = *(const ulonglong2*)&hlb[rl][32 + lo8];
                ulonglong2 lb = *(const ulonglong2*)&hlb[rl][32 + lo8 + 4];

                unsigned long long d0 = dup2(hv.x);
                unsigned long long d1 = dup2(hv.y);
                unsigned long long d2 = dup2(hv.z);
                unsigned long long d3 = dup2(hv.w);

                fma2(acc2[0][0], d0, la.x); fma2(acc2[0][1], d0, la.y);
                fma2(acc2[0][2], d0, lb.x); fma2(acc2[0][3], d0, lb.y);
                fma2(acc2[1][0], d1, la.x); fma2(acc2[1][1], d1, la.y);
                fma2(acc2[1][2], d1, lb.x); fma2(acc2[1][3], d1, lb.y);
                fma2(acc2[2][0], d2, la.x); fma2(acc2[2][1], d2, la.y);
                fma2(acc2[2][2], d2, lb.x); fma2(acc2[2][3], d2, lb.y);
                fma2(acc2[3][0], d3, la.x); fma2(acc2[3][1], d3, la.y);
                fma2(acc2[3][2], d3, lb.x); fma2(acc2[3][3], d3, lb.y);
            }
            __syncthreads();
        }

        #pragma unroll
        for (int i = 0; i < 4; i++) {
            #pragma unroll
            for (int j = 0; j < 4; j++) {
                float vlo = __uint_as_float((unsigned)(acc2[i][j] & 0xffffffffu));
                float vhi = __uint_as_float((unsigned)(acc2[i][j] >> 32));
                int code = (hi4 + i) * 32 + lo8 + 2 * j;
                atomicAdd(&codebuf[code], vlo);
                atomicAdd(&codebuf[code + 1], vhi);
            }
        }
        __syncthreads();
        for (int i = t; i < 1024; i += 256)
            atomicAdd(&g_codesum[q * 1024 + i], codebuf[i]);
    }
}

// ---------------------------------------------------------------------------
__global__ void k_fin(float* __restrict__ loss_out) {
    __shared__ float red[256];
    const int q = blockIdx.x;
    const int t = threadIdx.x;
    float e = 0.f;
    #pragma unroll
    for (int k = 0; k < 4; k++) {
        int c = k * 256 + t;
        float avg = g_codesum[q * 1024 + c] * (1.0f / (float)NROWS);
        e -= avg * __logf(fmaxf(avg, 1e-20f));
    }
    red[t] = e;
    __syncthreads();
    for (int s = 128; s > 0; s >>= 1) {
        if (t < s) red[t] += red[t + s];
        __syncthreads();
    }
    if (t == 0) {
        float per_sample = g_psent[q] * (1.0f / (float)NROWS);
        float ent_aux = per_sample - red[0];
        float commit = g_commit[q] * (1.0f / (float)(NROWS * CD));
        loss_out[q] = ent_aux * 0.1f + commit * 0.25f;
    }
}

// ---------------------------------------------------------------------------
extern "C" void kernel_launch(void* const* d_in, const int* in_sizes, int n_in,
                              void* d_out, int out_size) {
    const float* x     = (const float*)d_in[0];
    const float* w_in  = (const float*)d_in[1];
    const float* b_in  = (const float*)d_in[2];
    const float* w_out = (const float*)d_in[3];
    const float* b_out = (const float*)d_in[4];

    float* out  = (float*)d_out;
    float* idx  = out + OUT_ELEMS;
    float* loss = out + LOSS_OFFSET;

    k_zero<<<32, 256>>>();                        // 1
    k_pad<<<1, 32>>>();                           // 2
    k_pad<<<1, 32>>>();                           // 3
    kA<<<1024, 256>>>(x, w_in, b_in);             // 4  <- ncu slot
    kB<<<2048, 256>>>(idx);                       // 5
    k2c<<<1536, 256>>>(w_out, b_out, out);        // 6
    k_fin<<<8, 256>>>(loss);                      // 7
}

// round 13
// speedup vs baseline: 1.5116x; 1.1000x over previous
#include <cuda_runtime.h>
#include <math.h>
#include <stdint.h>

#define NROWS 65536
#define DIMV  512
#define CD    10
#define NQ    8
#define OUT_ELEMS   (NROWS * DIMV)
#define IDX_ELEMS   (NROWS * NQ)
#define LOSS_OFFSET (OUT_ELEMS + IDX_ELEMS)

#define NPAIRS    (NROWS / 2)     // 32768
#define KA_BLOCKS 296             // one full wave at occupancy 2
#define KA_WARPS  (KA_BLOCKS * 8) // 2368

__device__ __align__(16) float g_ptab[(size_t)NQ * NROWS * CD];  // [q][row][d]
__device__ __align__(16) float g_h[(size_t)NROWS * CD];          // [row][d]
__device__ __align__(16) float g_qo[(size_t)NROWS * CD];         // [row][d]
__device__ __align__(16) float g_codesum[NQ * 1024];
__device__ float g_psent[NQ];
__device__ float g_commit[NQ];

// packed f32x2 FMA (sm_100a)
__device__ __forceinline__ void fma2(unsigned long long& acc,
                                     unsigned long long a,
                                     unsigned long long b) {
    asm("fma.rn.f32x2 %0, %1, %2, %0;" : "+l"(acc) : "l"(a), "l"(b));
}
__device__ __forceinline__ unsigned long long dup2(float v) {
    unsigned long long r;
    asm("mov.b64 %0, {%1, %1};" : "=l"(r) : "f"(v));
    return r;
}

// ---------------------------------------------------------------------------
__global__ void k_zero() {
    int t = blockIdx.x * blockDim.x + threadIdx.x;
    if (t < NQ * 1024) g_codesum[t] = 0.f;
    if (t < NQ) { g_psent[t] = 0.f; g_commit[t] = 0.f; }
}

__global__ void k_pad() {}   // shifts ncu's profiled slot (slot 4) onto kB

// ---------------------------------------------------------------------------
// kA v6: persistent (one wave), rolled double-buffered pipeline.
// Warp = 2 rows/pair, ~14 pairs per warp -> pipeline cold-start 1/14.
// Math order identical to R11 (bit-exact h).
__global__ void __launch_bounds__(256, 2) kA(
    const float* __restrict__ x,
    const float* __restrict__ w_in,
    const float* __restrict__ b_in)
{
    __shared__ __align__(16) float ws_t[CD * DIMV];   // transposed w_in [d][col]
    __shared__ float bis[16];

    const int tid = threadIdx.x;
    for (int i = tid; i < DIMV; i += 256) {
        #pragma unroll
        for (int d = 0; d < CD; d++) ws_t[d * DIMV + i] = w_in[i * CD + d];
    }
    if (tid < CD) bis[tid] = b_in[tid];
    __syncthreads();

    const int lane = tid & 31;
    const unsigned FULL = 0xffffffffu;
    const int gwarp = blockIdx.x * 8 + (tid >> 5);    // 2368 warps

    // prologue: prefetch first pair
    float4 xc[2][4];
    {
        const float* xr = x + (size_t)(gwarp * 2) * DIMV;
        #pragma unroll
        for (int m = 0; m < 2; m++)
            #pragma unroll
            for (int k = 0; k < 4; k++)
                xc[m][k] = *(const float4*)(xr + (size_t)m * DIMV + k * 128 + lane * 4);
    }

    #pragma unroll 2
    for (int pair = gwarp; pair < NPAIRS; pair += KA_WARPS) {
        const int row0 = pair * 2;
        const int nxt = pair + KA_WARPS;

        // issue next pair's loads BEFORE consuming current registers
        float4 xn[2][4];
        if (nxt < NPAIRS) {
            const float* xr2 = x + (size_t)(nxt * 2) * DIMV;
            #pragma unroll
            for (int m = 0; m < 2; m++)
                #pragma unroll
                for (int k = 0; k < 4; k++)
                    xn[m][k] = *(const float4*)(xr2 + (size_t)m * DIMV + k * 128 + lane * 4);
        }

        // ---- compute current pair (identical order to R11) ----
        float h[2][CD];
        #pragma unroll
        for (int m = 0; m < 2; m++)
            #pragma unroll
            for (int d = 0; d < CD; d++) h[m][d] = 0.f;

        #pragma unroll
        for (int k = 0; k < 4; k++) {
            #pragma unroll
            for (int d = 0; d < CD; d++) {
                float4 w = *(const float4*)(ws_t + d * DIMV + k * 128 + lane * 4);
                #pragma unroll
                for (int m = 0; m < 2; m++) {
                    h[m][d] = fmaf(xc[m][k].x, w.x, h[m][d]);
                    h[m][d] = fmaf(xc[m][k].y, w.y, h[m][d]);
                    h[m][d] = fmaf(xc[m][k].z, w.z, h[m][d]);
                    h[m][d] = fmaf(xc[m][k].w, w.w, h[m][d]);
                }
            }
        }

        // 5-stage butterfly over 20 sums
        #pragma unroll
        for (int m = 0; m < 2; m++)
            #pragma unroll
            for (int d = 0; d < CD; d++)
                #pragma unroll
                for (int off = 16; off > 0; off >>= 1)
                    h[m][d] += __shfl_xor_sync(FULL, h[m][d], off);

        // lanes 0..19 store: m = lane/10, d = lane%10
        if (lane < 20) {
            int m = lane / 10;
            int d = lane - m * 10;
            float v = 0.f;
            #pragma unroll
            for (int mm = 0; mm < 2; mm++)
                #pragma unroll
                for (int dd = 0; dd < CD; dd++)
                    if (lane == mm * 10 + dd) v = h[mm][dd];
            g_h[(size_t)(row0 + m) * CD + d] = v + bis[d];
        }

        // rotate buffers (renamed away by unroll 2)
        #pragma unroll
        for (int m = 0; m < 2; m++)
            #pragma unroll
            for (int k = 0; k < 4; k++)
                xc[m][k] = xn[m][k];
    }
}

// ---------------------------------------------------------------------------
// kB: 8x LFQ on h. One quad per warp. (unchanged — known correct)
__global__ void __launch_bounds__(256, 4) kB(float* __restrict__ out_idx)
{
    __shared__ float red_ps[8][NQ];
    __shared__ float red_cm[8][NQ];

    const int tid = threadIdx.x;
    const int lane = tid & 31;
    const int wid  = tid >> 5;
    const int half = lane >> 4;
    const int hl   = lane & 15;
    const unsigned FULL = 0xffffffffu;

    const int quad = blockIdx.x * 8 + wid;
    const int row0 = quad * 4;
    const int row_a = row0 + 2 * half;

    float ra = 0.f, rb = 0.f;
    if (hl < CD) {
        ra = g_h[(size_t)row_a * CD + hl];
        rb = g_h[(size_t)(row_a + 1) * CD + hl];
    }

    float psent[NQ], commit[NQ];
    #pragma unroll
    for (int q = 0; q < NQ; q++) { psent[q] = 0.f; commit[q] = 0.f; }

    float qo_a = 0.f, qo_b = 0.f, iv_a = 0.f, iv_b = 0.f;

    #pragma unroll
    for (int q = 0; q < NQ; q++) {
        const float scale = 1.0f / (float)(1 << q);

        #define QSTEP(R, QO, IV, ROW)                                           \
        {                                                                       \
            bool pos = (R) > 0.f;                                               \
            unsigned bl = __ballot_sync(FULL, pos);                             \
            int idx = (int)(__brev((bl >> (half * 16)) & 0x3FFu) >> 22);        \
            if (hl == q) (IV) = (float)idx;                                     \
            float qv = pos ? scale : -scale;                                    \
            float dlt = (R) - qv;                                               \
            if (hl < CD) {                                                      \
                float a = 400.f * scale * (R);                                  \
                float t = fabsf(a);                                             \
                float e = __expf(-t);                                           \
                float inv = __fdividef(1.f, 1.f + e);                           \
                float p = (a > 0.f) ? inv : e * inv;                            \
                commit[q] += dlt * dlt;                                         \
                psent[q] += __logf(1.f + e) + t * e * inv;                      \
                g_ptab[((size_t)q * NROWS + (ROW)) * CD + hl] = p;              \
            }                                                                   \
            (R) = dlt;                                                          \
            (QO) += qv;                                                         \
        }

        QSTEP(ra, qo_a, iv_a, row_a)
        QSTEP(rb, qo_b, iv_b, row_a + 1)
        #undef QSTEP
    }

    if (hl < NQ) {
        out_idx[(size_t)row_a * NQ + hl]       = iv_a;
        out_idx[(size_t)(row_a + 1) * NQ + hl] = iv_b;
    }
    if (hl < CD) {
        g_qo[(size_t)row_a * CD + hl]       = qo_a;
        g_qo[(size_t)(row_a + 1) * CD + hl] = qo_b;
    }

    #pragma unroll
    for (int q = 0; q < NQ; q++) {
        float v = psent[q], c = commit[q];
        #pragma unroll
        for (int off = 16; off > 0; off >>= 1) {
            v += __shfl_xor_sync(FULL, v, off);
            c += __shfl_xor_sync(FULL, c, off);
        }
        if (lane == 0) { red_ps[wid][q] = v; red_cm[wid][q] = c; }
    }
    __syncthreads();
    if (tid < NQ * 2) {
        int q = tid & 7;
        bool isC = tid >= NQ;
        float s = 0.f;
        #pragma unroll
        for (int w = 0; w < 8; w++) s += isC ? red_cm[w][q] : red_ps[w][q];
        atomicAdd(isC ? &g_commit[q] : &g_psent[q], s);
    }
}

// ---------------------------------------------------------------------------
// k2c: fused. Blocks [0,512): out-GEMM. Blocks [512,1536): codesum. (unchanged)
__global__ void __launch_bounds__(256, 3) k2c(
    const float* __restrict__ w_out,
    const float* __restrict__ b_out,
    float* __restrict__ out)
{
    const int t = threadIdx.x;

    if (blockIdx.x < 512) {
        __shared__ __align__(16) float qo_s[128 * CD];
        const int j4 = t & 127;
        const int halfr = t >> 7;
        const int rows0 = blockIdx.x * 128;

        float4 w[CD];
        #pragma unroll
        for (int d = 0; d < CD; d++) w[d] = ((const float4*)w_out)[d * 128 + j4];
        float4 b4 = ((const float4*)b_out)[j4];

        const float4* src = (const float4*)(g_qo + (size_t)rows0 * CD);
        for (int i = t; i < 320; i += 256) ((float4*)qo_s)[i] = src[i];
        __syncthreads();

        float4* outv = (float4*)out;
        #pragma unroll 4
        for (int i = 0; i < 64; i += 2) {
            int r0 = 2 * i + halfr;
            int r1 = r0 + 2;
            float4 a0 = b4, a1 = b4;
            #pragma unroll
            for (int d = 0; d < CD; d++) {
                float q0 = qo_s[r0 * CD + d];
                float q1 = qo_s[r1 * CD + d];
                a0.x = fmaf(q0, w[d].x, a0.x);
                a0.y = fmaf(q0, w[d].y, a0.y);
                a0.z = fmaf(q0, w[d].z, a0.z);
                a0.w = fmaf(q0, w[d].w, a0.w);
                a1.x = fmaf(q1, w[d].x, a1.x);
                a1.y = fmaf(q1, w[d].y, a1.y);
                a1.z = fmaf(q1, w[d].z, a1.z);
                a1.w = fmaf(q1, w[d].w, a1.w);
            }
            outv[(size_t)(rows0 + r0) * 128 + j4] = a0;
            outv[(size_t)(rows0 + r1) * 128 + j4] = a1;
        }
    } else {
        const int b = blockIdx.x - 512;
        const int q = b >> 7;
        const int chunk = b & 127;
        const int row0 = chunk * 512;

        __shared__ float ps_s[32 * CD];
        __shared__ __align__(16) float hlb[32][64];
        __shared__ float codebuf[1024];

        for (int i = t; i < 1024; i += 256) codebuf[i] = 0.f;

        const int cls = t & 31;
        const int wid = t >> 5;
        const int hi4 = (cls >> 2) * 4;
        const int lo8 = (cls & 3) * 8;

        unsigned long long acc2[4][4];
        #pragma unroll
        for (int i = 0; i < 4; i++)
            #pragma unroll
            for (int j = 0; j < 4; j++) acc2[i][j] = 0ULL;

        const float* pt = g_ptab + (size_t)q * NROWS * CD + (size_t)row0 * CD;

        float nxt0 = pt[t];
        float nxt1 = (t < 64) ? pt[256 + t] : 0.f;

        for (int tile = 0; tile < 16; tile++) {
            ps_s[t] = nxt0;
            if (t < 64) ps_s[256 + t] = nxt1;
            __syncthreads();

            if (tile < 15) {
                const float* nb = pt + (tile + 1) * 320;
                nxt0 = nb[t];
                if (t < 64) nxt1 = nb[256 + t];
            }

            #pragma unroll
            for (int task = t; task < 512; task += 256) {
                int rl = task >> 4;
                int v0 = (task & 15) * 4;
                bool isHi = (v0 < 32);
                int dbase = isHi ? 0 : 5;
                int vb = isHi ? v0 : (v0 - 32);
                const float* pr = ps_s + rl * CD + dbase;
                float p0 = pr[0], p1 = pr[1], p2 = pr[2], p3 = pr[3], p4 = pr[4];
                float n0 = 1.f - p0, n1 = 1.f - p1, n2 = 1.f - p2, n3 = 1.f - p3, n4 = 1.f - p4;
                float4 res;
                float* rp = &res.x;
                #pragma unroll
                for (int j = 0; j < 4; j++) {
                    int v = vb + j;
                    float val = ((v & 16) ? p0 : n0);
                    val *= ((v & 8) ? p1 : n1);
                    val *= ((v & 4) ? p2 : n2);
                    val *= ((v & 2) ? p3 : n3);
                    val *= ((v & 1) ? p4 : n4);
                    rp[j] = val;
                }
                *(float4*)&hlb[rl][v0] = res;
            }
            __syncthreads();

            #pragma unroll
            for (int rr = 0; rr < 4; rr++) {
                int rl = wid * 4 + rr;
                float4 hv = *(const float4*)&hlb[rl][hi4];
                ulonglong2 la = *(const ulonglong2*)&hlb[rl][32 + lo8];
                ulonglong2 lb = *(const ulonglong2*)&hlb[rl][32 + lo8 + 4];

                unsigned long long d0 = dup2(hv.x);
                unsigned long long d1 = dup2(hv.y);
                unsigned long long d2 = dup2(hv.z);
                unsigned long long d3 = dup2(hv.w);

                fma2(acc2[0][0], d0, la.x); fma2(acc2[0][1], d0, la.y);
                fma2(acc2[0][2], d0, lb.x); fma2(acc2[0][3], d0, lb.y);
                fma2(acc2[1][0], d1, la.x); fma2(acc2[1][1], d1, la.y);
                fma2(acc2[1][2], d1, lb.x); fma2(acc2[1][3], d1, lb.y);
                fma2(acc2[2][0], d2, la.x); fma2(acc2[2][1], d2, la.y);
                fma2(acc2[2][2], d2, lb.x); fma2(acc2[2][3], d2, lb.y);
                fma2(acc2[3][0], d3, la.x); fma2(acc2[3][1], d3, la.y);
                fma2(acc2[3][2], d3, lb.x); fma2(acc2[3][3], d3, lb.y);
            }
            __syncthreads();
        }

        #pragma unroll
        for (int i = 0; i < 4; i++) {
            #pragma unroll
            for (int j = 0; j < 4; j++) {
                float vlo = __uint_as_float((unsigned)(acc2[i][j] & 0xffffffffu));
                float vhi = __uint_as_float((unsigned)(acc2[i][j] >> 32));
                int code = (hi4 + i) * 32 + lo8 + 2 * j;
                atomicAdd(&codebuf[code], vlo);
                atomicAdd(&codebuf[code + 1], vhi);
            }
        }
        __syncthreads();
        for (int i = t; i < 1024; i += 256)
            atomicAdd(&g_codesum[q * 1024 + i], codebuf[i]);
    }
}

// ---------------------------------------------------------------------------
__global__ void k_fin(float* __restrict__ loss_out) {
    __shared__ float red[256];
    const int q = blockIdx.x;
    const int t = threadIdx.x;
    float e = 0.f;
    #pragma unroll
    for (int k = 0; k < 4; k++) {
        int c = k * 256 + t;
        float avg = g_codesum[q * 1024 + c] * (1.0f / (float)NROWS);
        e -= avg * __logf(fmaxf(avg, 1e-20f));
    }
    red[t] = e;
    __syncthreads();
    for (int s = 128; s > 0; s >>= 1) {
        if (t < s) red[t] += red[t + s];
        __syncthreads();
    }
    if (t == 0) {
        float per_sample = g_psent[q] * (1.0f / (float)NROWS);
        float ent_aux = per_sample - red[0];
        float commit = g_commit[q] * (1.0f / (float)(NROWS * CD));
        loss_out[q] = ent_aux * 0.1f + commit * 0.25f;
    }
}

// ---------------------------------------------------------------------------
extern "C" void kernel_launch(void* const* d_in, const int* in_sizes, int n_in,
                              void* d_out, int out_size) {
    const float* x     = (const float*)d_in[0];
    const float* w_in  = (const float*)d_in[1];
    const float* b_in  = (const float*)d_in[2];
    const float* w_out = (const float*)d_in[3];
    const float* b_out = (const float*)d_in[4];

    float* out  = (float*)d_out;
    float* idx  = out + OUT_ELEMS;
    float* loss = out + LOSS_OFFSET;

    k_zero<<<32, 256>>>();                        // 1
    k_pad<<<1, 32>>>();                           // 2
    kA<<<KA_BLOCKS, 256>>>(x, w_in, b_in);        // 3
    kB<<<2048, 256>>>(idx);                       // 4  <- ncu slot
    k2c<<<1536, 256>>>(w_out, b_out, out);        // 5
    k_fin<<<8, 256>>>(loss);                      // 6
}